// round 1
// baseline (speedup 1.0000x reference)
#include <cuda_runtime.h>
#include <cstdint>

// Problem constants
#define Dc     256        // feature dim
#define Kc     1024       // codebook size
#define HWc    1024       // 32*32
#define NTOK   65536      // 64 * 1024 tokens
#define NELEM  16777216   // 64*256*32*32

// GEMM tiling
#define BM 64     // tokens per block
#define BN 64     // codes per chunk
#define BK 16     // d per stage
#define NTHREADS 256

__device__ float    g_cnorm[Kc];
__device__ int      g_idx[NTOK];

// ---------------------------------------------------------------------------
// Kernel 1: ||c_k||^2 per code. One warp per code.
// ---------------------------------------------------------------------------
__global__ void cnorm_kernel(const float* __restrict__ cb) {
    int warp = (blockIdx.x * blockDim.x + threadIdx.x) >> 5;
    int lane = threadIdx.x & 31;
    if (warp >= Kc) return;
    const float* row = cb + warp * Dc;
    float s = 0.f;
    #pragma unroll
    for (int d = lane; d < Dc; d += 32) {
        float v = row[d];
        s = fmaf(v, v, s);
    }
    #pragma unroll
    for (int o = 16; o; o >>= 1) s += __shfl_xor_sync(0xFFFFFFFFu, s, o);
    if (lane == 0) g_cnorm[warp] = s;
}

// ---------------------------------------------------------------------------
// orderable-uint transform: smaller float <-> smaller uint (handles negatives)
// ---------------------------------------------------------------------------
__device__ __forceinline__ unsigned int fkey(float f) {
    unsigned int u = __float_as_uint(f);
    return (u & 0x80000000u) ? ~u : (u | 0x80000000u);
}

// ---------------------------------------------------------------------------
// Kernel 2: fused GEMM + running argmin.
// Block = 64 tokens. Loops over 16 chunks of 64 codes; per chunk a full
// D=256 dot is accumulated with a 64x64 SGEMM tile (4x4 per-thread tile).
// Each thread keeps a running (score,idx) best for its 4 token-rows across
// all chunks; single smem atomicMin reduction at the end.
// ---------------------------------------------------------------------------
__global__ __launch_bounds__(NTHREADS) void argmin_kernel(
    const float* __restrict__ x, const float* __restrict__ cb)
{
    __shared__ float As[BK * BM];               // [k][m]
    __shared__ float Bs[BK * BN];               // [k][n]
    __shared__ unsigned long long sBest[BM];

    const int tid  = threadIdx.x;
    const int trow = tid >> 4;        // 0..15  -> token group
    const int tcol = tid & 15;        // 0..15  -> code group

    const int n0  = blockIdx.x * BM;  // first token of this block
    const int b   = n0 >> 10;         // batch index (64 tokens always same b)
    const int hw0 = n0 & (HWc - 1);
    const float* xb = x + (size_t)b * Dc * HWc + hw0;  // (m,d) at xb[d*HWc + m]

    if (tid < BM) sBest[tid] = 0xFFFFFFFFFFFFFFFFull;

    // A-tile load mapping: one float4 per thread, k = tid/16, m4 = (tid%16)*4
    const int a_k  = tid >> 4;
    const int a_m4 = (tid & 15) << 2;
    // B-tile load mapping: n = tid/4, k4 = (tid%4)*4
    const int b_n  = tid >> 2;
    const int b_k4 = (tid & 3) << 2;

    float bestScore[4];
    int   bestIdx[4];
    #pragma unroll
    for (int i = 0; i < 4; i++) { bestScore[i] = 3.4e38f; bestIdx[i] = 0; }

    for (int c = 0; c < Kc / BN; c++) {
        const int c0 = c * BN;
        float acc[4][4];
        #pragma unroll
        for (int i = 0; i < 4; i++)
            #pragma unroll
            for (int j = 0; j < 4; j++) acc[i][j] = 0.f;

        for (int dstep = 0; dstep < Dc / BK; dstep++) {
            const int d0 = dstep * BK;
            __syncthreads();
            // load A: coalesced along hw (token) dimension
            {
                float4 v = *reinterpret_cast<const float4*>(
                    xb + (size_t)(d0 + a_k) * HWc + a_m4);
                *reinterpret_cast<float4*>(&As[a_k * BM + a_m4]) = v;
            }
            // load B: float4 along d, scatter into [k][n]
            {
                float4 v = *reinterpret_cast<const float4*>(
                    cb + (size_t)(c0 + b_n) * Dc + d0 + b_k4);
                Bs[(b_k4 + 0) * BN + b_n] = v.x;
                Bs[(b_k4 + 1) * BN + b_n] = v.y;
                Bs[(b_k4 + 2) * BN + b_n] = v.z;
                Bs[(b_k4 + 3) * BN + b_n] = v.w;
            }
            __syncthreads();

            #pragma unroll
            for (int kk = 0; kk < BK; kk++) {
                float4 a = *reinterpret_cast<const float4*>(&As[kk * BM + trow * 4]);
                float4 bv = *reinterpret_cast<const float4*>(&Bs[kk * BN + tcol * 4]);
                float ar[4] = {a.x, a.y, a.z, a.w};
                float br[4] = {bv.x, bv.y, bv.z, bv.w};
                #pragma unroll
                for (int i = 0; i < 4; i++)
                    #pragma unroll
                    for (int j = 0; j < 4; j++)
                        acc[i][j] = fmaf(ar[i], br[j], acc[i][j]);
            }
        }

        // fold chunk scores into running best
        #pragma unroll
        for (int j = 0; j < 4; j++) {
            const int code = c0 + tcol * 4 + j;
            const float cn = g_cnorm[code];
            #pragma unroll
            for (int i = 0; i < 4; i++) {
                float score = fmaf(-2.f, acc[i][j], cn);
                if (score < bestScore[i]) { bestScore[i] = score; bestIdx[i] = code; }
            }
        }
    }

    __syncthreads();
    #pragma unroll
    for (int i = 0; i < 4; i++) {
        int m = trow * 4 + i;
        unsigned long long pack =
            ((unsigned long long)fkey(bestScore[i]) << 32) | (unsigned int)bestIdx[i];
        atomicMin(&sBest[m], pack);
    }
    __syncthreads();
    if (tid < BM)
        g_idx[n0 + tid] = (int)(unsigned int)(sBest[tid] & 0xFFFFFFFFull);
}

// ---------------------------------------------------------------------------
// Kernel 3: fused gather + straight-through output.
// z_q flat[j] = cb[idx[j/256] * 256 + j%256]   (raw NHWC->BCHW reshape)
// z_hat[j]    = x[j] + (z_q[j] - x[j])
// One float4 per thread.
// ---------------------------------------------------------------------------
__global__ void output_kernel(const float* __restrict__ x,
                              const float* __restrict__ cb,
                              float* __restrict__ zhat,
                              float* __restrict__ zq)
{
    int t = blockIdx.x * blockDim.x + threadIdx.x;   // float4 index
    if (t >= NELEM / 4) return;
    int n  = t >> 6;          // 64 float4 per token
    int d4 = t & 63;
    int k  = g_idx[n];
    float4 c  = *reinterpret_cast<const float4*>(cb + (size_t)k * Dc + d4 * 4);
    float4 xv = *reinterpret_cast<const float4*>(x + (size_t)t * 4);
    float4 zh;
    zh.x = xv.x + (c.x - xv.x);
    zh.y = xv.y + (c.y - xv.y);
    zh.z = xv.z + (c.z - xv.z);
    zh.w = xv.w + (c.w - xv.w);
    *reinterpret_cast<float4*>(zq   + (size_t)t * 4) = c;
    *reinterpret_cast<float4*>(zhat + (size_t)t * 4) = zh;
}

// ---------------------------------------------------------------------------
extern "C" void kernel_launch(void* const* d_in, const int* in_sizes, int n_in,
                              void* d_out, int out_size)
{
    const float* x  = (const float*)d_in[0];   // [64,256,32,32]
    const float* cb = (const float*)d_in[1];   // [1024,256]
    float* zhat = (float*)d_out;               // first NELEM floats
    float* zq   = (float*)d_out + NELEM;       // second NELEM floats

    cnorm_kernel<<<Kc / 8, 256>>>(cb);                       // 8 warps/block
    argmin_kernel<<<NTOK / BM, NTHREADS>>>(x, cb);
    output_kernel<<<(NELEM / 4 + 255) / 256, 256>>>(x, cb, zhat, zq);
}

// round 3
// speedup vs baseline: 2.5392x; 2.5392x over previous
#include <cuda_runtime.h>
#include <cuda_fp16.h>
#include <cstdint>

// Problem constants
#define Dc     256
#define Kc     1024
#define HWc    1024
#define NTOK   65536
#define NELEM  16777216

#define NBLK   512          // token blocks of 128
#define M_TILE 128
#define NCHUNK 8            // 1024 / 128 codes per chunk
#define NSTG   8            // 8 k-stages of 32 per 256-d

// gA: [512 bm][2 plane][8 stage][128 rows][64B]  (fp16, linear)  = 64 MB
// gB: [8 nc][2 plane][8 stage][128 rows][64B]                     = 1 MB
__device__ __align__(128) unsigned char gA[(size_t)NBLK * 131072];
__device__ __align__(128) unsigned char gB[8 * 2 * 8 * 8192];
__device__ float g_cnorm[Kc];
__device__ int   g_idx[NTOK];

// dynamic smem layout (argmin kernel)
#define SM_A     0          // 16 tiles x 8192 = 128KB  ([plane][stage])
#define SM_B     131072     // 3 bufs x 8192 = 24KB
#define SM_CN    155648     // 4KB
#define SM_BEST  159744     // 1KB
#define SM_TOTAL 160768

__device__ __forceinline__ uint32_t smem_u32(const void* p) {
    uint32_t a;
    asm("{ .reg .u64 t; cvta.to.shared.u64 t, %1; cvt.u32.u64 %0, t; }" : "=r"(a) : "l"(p));
    return a;
}
__device__ __forceinline__ void cp16(uint32_t dst, const void* src) {
    asm volatile("cp.async.cg.shared.global [%0], [%1], 16;" :: "r"(dst), "l"(src) : "memory");
}
__device__ __forceinline__ void cp_commit() {
    asm volatile("cp.async.commit_group;" ::: "memory");
}
__device__ __forceinline__ void cp_wait1() {
    asm volatile("cp.async.wait_group 1;" ::: "memory");
}
__device__ __forceinline__ void cp_wait0() {
    asm volatile("cp.async.wait_group 0;" ::: "memory");
}
__device__ __forceinline__ void ldsm4(uint32_t& r0, uint32_t& r1, uint32_t& r2, uint32_t& r3,
                                      uint32_t addr) {
    asm volatile("ldmatrix.sync.aligned.m8n8.x4.shared.b16 {%0,%1,%2,%3}, [%4];"
                 : "=r"(r0), "=r"(r1), "=r"(r2), "=r"(r3) : "r"(addr));
}
__device__ __forceinline__ void mma16816(float& c0, float& c1, float& c2, float& c3,
                                         uint32_t a0, uint32_t a1, uint32_t a2, uint32_t a3,
                                         uint32_t b0, uint32_t b1) {
    asm volatile("mma.sync.aligned.m16n8k16.row.col.f32.f16.f16.f32 "
                 "{%0,%1,%2,%3}, {%4,%5,%6,%7}, {%8,%9}, {%0,%1,%2,%3};"
                 : "+f"(c0), "+f"(c1), "+f"(c2), "+f"(c3)
                 : "r"(a0), "r"(a1), "r"(a2), "r"(a3), "r"(b0), "r"(b1));
}
__device__ __forceinline__ unsigned int fkey(float f) {
    unsigned int u = __float_as_uint(f);
    return (u & 0x80000000u) ? ~u : (u | 0x80000000u);
}
__device__ __forceinline__ uint32_t pkh(float a, float b) {
    __half h0 = __float2half_rn(a), h1 = __float2half_rn(b);
    return (uint32_t)__half_as_ushort(h0) | ((uint32_t)__half_as_ushort(h1) << 16);
}

// ---------------------------------------------------------------------------
// prep A: x (b,d,hw) -> token-major fp16 hi/lo planes, stage-blocked linear.
// grid (512, 8): (bm, stage). 32 d x 128 hw transpose in smem.
// ---------------------------------------------------------------------------
__global__ __launch_bounds__(256) void prep_a(const float* __restrict__ x) {
    __shared__ float xs[32][132];
    const int bm = blockIdx.x, stage = blockIdx.y;
    const int b = bm >> 3, hw0 = (bm & 7) << 7, d0 = stage << 5;
    const float* xb = x + ((size_t)b * Dc + d0) * HWc + hw0;

    for (int i = threadIdx.x; i < 1024; i += 256) {
        int d = i >> 5, q = i & 31;
        float4 v = *reinterpret_cast<const float4*>(xb + (size_t)d * HWc + q * 4);
        xs[d][4*q] = v.x; xs[d][4*q+1] = v.y; xs[d][4*q+2] = v.z; xs[d][4*q+3] = v.w;
    }
    __syncthreads();

    unsigned char* outHi = gA + (size_t)bm * 131072 + (size_t)stage * 8192;
    unsigned char* outLo = outHi + 8 * 8192;
    #pragma unroll
    for (int v = 0; v < 2; v++) {
        int id = v * 256 + threadIdx.x;     // 512 16B units: r = id>>2, u = id&3
        int r = id >> 2, u = id & 3;
        uint32_t hw_[4], lw_[4];
        #pragma unroll
        for (int p = 0; p < 4; p++) {
            float v0 = xs[u*8 + 2*p][r], v1 = xs[u*8 + 2*p + 1][r];
            __half h0 = __float2half_rn(v0), h1 = __float2half_rn(v1);
            float l0 = v0 - __half2float(h0), l1 = v1 - __half2float(h1);
            hw_[p] = (uint32_t)__half_as_ushort(h0) | ((uint32_t)__half_as_ushort(h1) << 16);
            lw_[p] = pkh(l0, l1);
        }
        *reinterpret_cast<uint4*>(outHi + (size_t)id * 16) = make_uint4(hw_[0], hw_[1], hw_[2], hw_[3]);
        *reinterpret_cast<uint4*>(outLo + (size_t)id * 16) = make_uint4(lw_[0], lw_[1], lw_[2], lw_[3]);
    }
}

// ---------------------------------------------------------------------------
// prep B: codebook -> fp16 hi/lo stage-blocked linear. grid (8 nc, 8 stage)
// ---------------------------------------------------------------------------
__global__ __launch_bounds__(256) void prep_b(const float* __restrict__ cb) {
    const int nc = blockIdx.x, stage = blockIdx.y;
    unsigned char* outHi = gB + ((size_t)(nc * 2 + 0) * 8 + stage) * 8192;
    unsigned char* outLo = gB + ((size_t)(nc * 2 + 1) * 8 + stage) * 8192;
    #pragma unroll
    for (int v = 0; v < 2; v++) {
        int id = v * 256 + threadIdx.x;
        int r = id >> 2, u = id & 3;
        const float* src = cb + (size_t)(nc * 128 + r) * Dc + stage * 32 + u * 8;
        uint32_t hw_[4], lw_[4];
        #pragma unroll
        for (int p = 0; p < 4; p++) {
            float v0 = src[2*p], v1 = src[2*p + 1];
            __half h0 = __float2half_rn(v0), h1 = __float2half_rn(v1);
            float l0 = v0 - __half2float(h0), l1 = v1 - __half2float(h1);
            hw_[p] = (uint32_t)__half_as_ushort(h0) | ((uint32_t)__half_as_ushort(h1) << 16);
            lw_[p] = pkh(l0, l1);
        }
        *reinterpret_cast<uint4*>(outHi + (size_t)id * 16) = make_uint4(hw_[0], hw_[1], hw_[2], hw_[3]);
        *reinterpret_cast<uint4*>(outLo + (size_t)id * 16) = make_uint4(lw_[0], lw_[1], lw_[2], lw_[3]);
    }
}

// ---------------------------------------------------------------------------
__global__ void cnorm_kernel(const float* __restrict__ cb) {
    int warp = (blockIdx.x * blockDim.x + threadIdx.x) >> 5;
    int lane = threadIdx.x & 31;
    if (warp >= Kc) return;
    const float* row = cb + warp * Dc;
    float s = 0.f;
    #pragma unroll
    for (int d = lane; d < Dc; d += 32) { float v = row[d]; s = fmaf(v, v, s); }
    #pragma unroll
    for (int o = 16; o; o >>= 1) s += __shfl_xor_sync(0xFFFFFFFFu, s, o);
    if (lane == 0) g_cnorm[warp] = s;
}

// ---------------------------------------------------------------------------
// argmin via mma.sync: 512 CTAs x 256 thr (8 warps, 2x4 warp grid, 64x32
// warp tiles). A (hi+lo) smem-resident; B streamed (3-buf cp.async pipe).
// 3-term fp16-split: hi*hi + lo_x*hi_c (B-hi stages) + hi_x*lo_c (B-lo).
// Per-thread running argmin across chunks; one smem atomicMin fold at end.
// ---------------------------------------------------------------------------
__global__ __launch_bounds__(256, 1) void argmin_mma() {
    extern __shared__ __align__(128) unsigned char smem[];
    const uint32_t sb = smem_u32(smem);
    const int tid = threadIdx.x, lane = tid & 31, wid = tid >> 5;
    const int wm = wid & 1, wn = wid >> 1;
    const int bm = blockIdx.x;

    float* sm_cn = reinterpret_cast<float*>(smem + SM_CN);
    unsigned long long* sBest = reinterpret_cast<unsigned long long*>(smem + SM_BEST);
    for (int i = tid; i < Kc; i += 256) sm_cn[i] = g_cnorm[i];
    if (tid < 128) sBest[tid] = ~0ull;

    // A image -> smem (swizzle applied at cp.async dst)
    {
        const unsigned char* src = gA + (size_t)bm * 131072;
        #pragma unroll
        for (int v = 0; v < 32; v++) {
            int id = v * 256 + tid;
            int tile = id >> 9, r = (id >> 2) & 127, u = id & 3;
            uint32_t dst = sb + SM_A + tile * 8192 + r * 64 + 16 * (u ^ ((r >> 1) & 3));
            cp16(dst, src + (size_t)id * 16);
        }
        cp_commit();
    }

    // lane-fixed fragment address components
    const int a_r   = wm * 64 + (lane & 15);       // + mi*16
    const int a_u   = lane >> 4;                   // + kk*2
    const int b_r   = wn * 32 + (lane & 7) + ((lane >> 4) << 3);  // + np*16
    const int b_u   = (lane >> 3) & 1;             // + kk*2

    float best8[8];
    int   bid8[8];
    #pragma unroll
    for (int i = 0; i < 8; i++) { best8[i] = 3.4e38f; bid8[i] = 0; }

    #pragma unroll 1
    for (int nc = 0; nc < NCHUNK; nc++) {
        float acc[4][4][4];
        #pragma unroll
        for (int mi = 0; mi < 4; mi++)
            #pragma unroll
            for (int ni = 0; ni < 4; ni++)
                #pragma unroll
                for (int c = 0; c < 4; c++) acc[mi][ni][c] = 0.f;

        // issue B stage t: plane = t>>3 (0=hi,1=lo), stage = t&7
        auto issueB = [&](int t) {
            int pa = t >> 3, s = t & 7;
            const unsigned char* src = gB + ((size_t)(nc * 2 + pa) * 8 + s) * 8192;
            uint32_t bufb = sb + SM_B + (t % 3) * 8192;
            #pragma unroll
            for (int v = 0; v < 2; v++) {
                int id = v * 256 + tid;
                int r = id >> 2, u = id & 3;
                cp16(bufb + r * 64 + 16 * (u ^ ((r >> 1) & 3)), src + (size_t)id * 16);
            }
            cp_commit();
        };

        issueB(0); issueB(1);

        #pragma unroll 1
        for (int t = 0; t < 16; t++) {
            if (t < 15) cp_wait1(); else cp_wait0();
            __syncthreads();
            if (t + 2 < 16) issueB(t + 2);

            const int s = t & 7;
            const int bhi = (t < 8);
            const uint32_t SBb = sb + SM_B + (t % 3) * 8192;

            #pragma unroll
            for (int kk = 0; kk < 2; kk++) {
                // B fragments: np=0 -> br[0..3] covers ni 0,1 ; np=1 -> ni 2,3
                uint32_t br[8];
                #pragma unroll
                for (int np = 0; np < 2; np++) {
                    int r = b_r + np * 16;
                    int c = kk * 2 + b_u;
                    uint32_t addr = SBb + r * 64 + 16 * (c ^ ((r >> 1) & 3));
                    ldsm4(br[np*4+0], br[np*4+1], br[np*4+2], br[np*4+3], addr);
                }
                // passes: B-hi pairs with A-hi and A-lo; B-lo pairs with A-hi
                const int npass = bhi ? 2 : 1;
                for (int pa = 0; pa < npass; pa++) {
                    const uint32_t SA = sb + SM_A + (pa * 8 + s) * 8192;
                    uint32_t ar[16];
                    #pragma unroll
                    for (int mi = 0; mi < 4; mi++) {
                        int r = a_r + mi * 16;
                        int c = kk * 2 + a_u;
                        uint32_t addr = SA + r * 64 + 16 * (c ^ ((r >> 1) & 3));
                        ldsm4(ar[mi*4+0], ar[mi*4+1], ar[mi*4+2], ar[mi*4+3], addr);
                    }
                    #pragma unroll
                    for (int mi = 0; mi < 4; mi++)
                        #pragma unroll
                        for (int ni = 0; ni < 4; ni++)
                            mma16816(acc[mi][ni][0], acc[mi][ni][1], acc[mi][ni][2], acc[mi][ni][3],
                                     ar[mi*4+0], ar[mi*4+1], ar[mi*4+2], ar[mi*4+3],
                                     br[(ni>>1)*4 + (ni&1)*2], br[(ni>>1)*4 + (ni&1)*2 + 1]);
                }
            }
        }

        // epilogue: fold chunk scores into running per-thread best
        #pragma unroll
        for (int mi = 0; mi < 4; mi++)
            #pragma unroll
            for (int ni = 0; ni < 4; ni++)
                #pragma unroll
                for (int c = 0; c < 4; c++) {
                    int code = nc * 128 + wn * 32 + ni * 8 + (lane & 3) * 2 + (c & 1);
                    float score = fmaf(-2.f, acc[mi][ni][c], sm_cn[code]);
                    int slot = mi * 2 + (c >> 1);
                    if (score < best8[slot]) { best8[slot] = score; bid8[slot] = code; }
                }
    }

    __syncthreads();
    #pragma unroll
    for (int slot = 0; slot < 8; slot++) {
        int row = wm * 64 + (slot >> 1) * 16 + (lane >> 2) + 8 * (slot & 1);
        unsigned long long pack =
            ((unsigned long long)fkey(best8[slot]) << 32) | (unsigned int)bid8[slot];
        atomicMin(&sBest[row], pack);
    }
    __syncthreads();
    if (tid < 128)
        g_idx[bm * M_TILE + tid] = (int)(unsigned int)(sBest[tid] & 0xFFFFFFFFull);
}

// ---------------------------------------------------------------------------
__global__ void output_kernel(const float* __restrict__ x,
                              const float* __restrict__ cb,
                              float* __restrict__ zhat,
                              float* __restrict__ zq)
{
    int t = blockIdx.x * blockDim.x + threadIdx.x;
    if (t >= NELEM / 4) return;
    int n  = t >> 6;
    int d4 = t & 63;
    int k  = g_idx[n];
    float4 c  = *reinterpret_cast<const float4*>(cb + (size_t)k * Dc + d4 * 4);
    float4 xv = *reinterpret_cast<const float4*>(x + (size_t)t * 4);
    float4 zh;
    zh.x = xv.x + (c.x - xv.x);
    zh.y = xv.y + (c.y - xv.y);
    zh.z = xv.z + (c.z - xv.z);
    zh.w = xv.w + (c.w - xv.w);
    *reinterpret_cast<float4*>(zq   + (size_t)t * 4) = c;
    *reinterpret_cast<float4*>(zhat + (size_t)t * 4) = zh;
}

// ---------------------------------------------------------------------------
extern "C" void kernel_launch(void* const* d_in, const int* in_sizes, int n_in,
                              void* d_out, int out_size)
{
    const float* x  = (const float*)d_in[0];
    const float* cb = (const float*)d_in[1];
    float* zhat = (float*)d_out;
    float* zq   = (float*)d_out + NELEM;

    static int attr_set = 0;
    if (!attr_set) {
        cudaFuncSetAttribute(argmin_mma, cudaFuncAttributeMaxDynamicSharedMemorySize, SM_TOTAL);
        attr_set = 1;
    }

    prep_a<<<dim3(NBLK, NSTG), 256>>>(x);
    prep_b<<<dim3(8, NSTG), 256>>>(cb);
    cnorm_kernel<<<Kc / 8, 256>>>(cb);
    argmin_mma<<<NBLK, 256, SM_TOTAL>>>();
    output_kernel<<<(NELEM / 4 + 255) / 256, 256>>>(x, cb, zhat, zq);
}

// round 4
// speedup vs baseline: 2.9527x; 1.1628x over previous
#include <cuda_runtime.h>
#include <cuda_fp16.h>
#include <cstdint>

// Problem constants
#define Dc     256
#define Kc     1024
#define HWc    1024
#define NTOK   65536
#define NELEM  16777216

#define NBLK   512          // token blocks of 128
#define M_TILE 128
#define NCHUNK 8            // 1024 / 128 codes per chunk
#define NSTG   8            // 8 k-stages of 32 per 256-d
#define TSTAGE 64           // flat stages = NCHUNK * NSTG

// gA: [512 bm][2 plane][8 stage][128 rows][64B]  (fp16, linear)  = 64 MB
// gB: [8 nc][2 plane][8 stage][128 rows][64B]                     = 1 MB
__device__ __align__(128) unsigned char gA[(size_t)NBLK * 131072];
__device__ __align__(128) unsigned char gB[8 * 2 * 8 * 8192];
__device__ float g_cnorm[Kc];
__device__ int   g_idx[NTOK];

// dynamic smem layout (argmin kernel)
#define SM_A     0          // 16 tiles x 8192 = 128KB  ([plane][stage])
#define SM_B     131072     // ring: 4 bufs x 16KB (hi 8KB + lo 8KB) = 64KB
#define SM_CN    196608     // 4KB
#define SM_BEST  200704     // 1KB
#define SM_TOTAL 201728

__device__ __forceinline__ uint32_t smem_u32(const void* p) {
    uint32_t a;
    asm("{ .reg .u64 t; cvta.to.shared.u64 t, %1; cvt.u32.u64 %0, t; }" : "=r"(a) : "l"(p));
    return a;
}
__device__ __forceinline__ void cp16(uint32_t dst, const void* src) {
    asm volatile("cp.async.cg.shared.global [%0], [%1], 16;" :: "r"(dst), "l"(src) : "memory");
}
__device__ __forceinline__ void cp_commit() {
    asm volatile("cp.async.commit_group;" ::: "memory");
}
__device__ __forceinline__ void cp_wait2() { asm volatile("cp.async.wait_group 2;" ::: "memory"); }
__device__ __forceinline__ void cp_wait1() { asm volatile("cp.async.wait_group 1;" ::: "memory"); }
__device__ __forceinline__ void cp_wait0() { asm volatile("cp.async.wait_group 0;" ::: "memory"); }

__device__ __forceinline__ void ldsm4(uint32_t& r0, uint32_t& r1, uint32_t& r2, uint32_t& r3,
                                      uint32_t addr) {
    asm volatile("ldmatrix.sync.aligned.m8n8.x4.shared.b16 {%0,%1,%2,%3}, [%4];"
                 : "=r"(r0), "=r"(r1), "=r"(r2), "=r"(r3) : "r"(addr));
}
__device__ __forceinline__ void mma16816(float& c0, float& c1, float& c2, float& c3,
                                         uint32_t a0, uint32_t a1, uint32_t a2, uint32_t a3,
                                         uint32_t b0, uint32_t b1) {
    asm volatile("mma.sync.aligned.m16n8k16.row.col.f32.f16.f16.f32 "
                 "{%0,%1,%2,%3}, {%4,%5,%6,%7}, {%8,%9}, {%0,%1,%2,%3};"
                 : "+f"(c0), "+f"(c1), "+f"(c2), "+f"(c3)
                 : "r"(a0), "r"(a1), "r"(a2), "r"(a3), "r"(b0), "r"(b1));
}
__device__ __forceinline__ unsigned int fkey(float f) {
    unsigned int u = __float_as_uint(f);
    return (u & 0x80000000u) ? ~u : (u | 0x80000000u);
}
__device__ __forceinline__ uint32_t pkh(float a, float b) {
    __half h0 = __float2half_rn(a), h1 = __float2half_rn(b);
    return (uint32_t)__half_as_ushort(h0) | ((uint32_t)__half_as_ushort(h1) << 16);
}

// ---------------------------------------------------------------------------
// prep A: x (b,d,hw) -> token-major fp16 hi/lo planes, stage-blocked linear.
// ---------------------------------------------------------------------------
__global__ __launch_bounds__(256) void prep_a(const float* __restrict__ x) {
    __shared__ float xs[32][132];
    const int bm = blockIdx.x, stage = blockIdx.y;
    const int b = bm >> 3, hw0 = (bm & 7) << 7, d0 = stage << 5;
    const float* xb = x + ((size_t)b * Dc + d0) * HWc + hw0;

    for (int i = threadIdx.x; i < 1024; i += 256) {
        int d = i >> 5, q = i & 31;
        float4 v = *reinterpret_cast<const float4*>(xb + (size_t)d * HWc + q * 4);
        xs[d][4*q] = v.x; xs[d][4*q+1] = v.y; xs[d][4*q+2] = v.z; xs[d][4*q+3] = v.w;
    }
    __syncthreads();

    unsigned char* outHi = gA + (size_t)bm * 131072 + (size_t)stage * 8192;
    unsigned char* outLo = outHi + 8 * 8192;
    #pragma unroll
    for (int v = 0; v < 2; v++) {
        int id = v * 256 + threadIdx.x;
        int r = id >> 2, u = id & 3;
        uint32_t hw_[4], lw_[4];
        #pragma unroll
        for (int p = 0; p < 4; p++) {
            float v0 = xs[u*8 + 2*p][r], v1 = xs[u*8 + 2*p + 1][r];
            __half h0 = __float2half_rn(v0), h1 = __float2half_rn(v1);
            float l0 = v0 - __half2float(h0), l1 = v1 - __half2float(h1);
            hw_[p] = (uint32_t)__half_as_ushort(h0) | ((uint32_t)__half_as_ushort(h1) << 16);
            lw_[p] = pkh(l0, l1);
        }
        *reinterpret_cast<uint4*>(outHi + (size_t)id * 16) = make_uint4(hw_[0], hw_[1], hw_[2], hw_[3]);
        *reinterpret_cast<uint4*>(outLo + (size_t)id * 16) = make_uint4(lw_[0], lw_[1], lw_[2], lw_[3]);
    }
}

// ---------------------------------------------------------------------------
// prep B: codebook -> fp16 hi/lo stage-blocked linear. grid (8 nc, 8 stage)
// ---------------------------------------------------------------------------
__global__ __launch_bounds__(256) void prep_b(const float* __restrict__ cb) {
    const int nc = blockIdx.x, stage = blockIdx.y;
    unsigned char* outHi = gB + ((size_t)(nc * 2 + 0) * 8 + stage) * 8192;
    unsigned char* outLo = gB + ((size_t)(nc * 2 + 1) * 8 + stage) * 8192;
    #pragma unroll
    for (int v = 0; v < 2; v++) {
        int id = v * 256 + threadIdx.x;
        int r = id >> 2, u = id & 3;
        const float* src = cb + (size_t)(nc * 128 + r) * Dc + stage * 32 + u * 8;
        uint32_t hw_[4], lw_[4];
        #pragma unroll
        for (int p = 0; p < 4; p++) {
            float v0 = src[2*p], v1 = src[2*p + 1];
            __half h0 = __float2half_rn(v0), h1 = __float2half_rn(v1);
            float l0 = v0 - __half2float(h0), l1 = v1 - __half2float(h1);
            hw_[p] = (uint32_t)__half_as_ushort(h0) | ((uint32_t)__half_as_ushort(h1) << 16);
            lw_[p] = pkh(l0, l1);
        }
        *reinterpret_cast<uint4*>(outHi + (size_t)id * 16) = make_uint4(hw_[0], hw_[1], hw_[2], hw_[3]);
        *reinterpret_cast<uint4*>(outLo + (size_t)id * 16) = make_uint4(lw_[0], lw_[1], lw_[2], lw_[3]);
    }
}

// ---------------------------------------------------------------------------
__global__ void cnorm_kernel(const float* __restrict__ cb) {
    int warp = (blockIdx.x * blockDim.x + threadIdx.x) >> 5;
    int lane = threadIdx.x & 31;
    if (warp >= Kc) return;
    const float* row = cb + warp * Dc;
    float s = 0.f;
    #pragma unroll
    for (int d = lane; d < Dc; d += 32) { float v = row[d]; s = fmaf(v, v, s); }
    #pragma unroll
    for (int o = 16; o; o >>= 1) s += __shfl_xor_sync(0xFFFFFFFFu, s, o);
    if (lane == 0) g_cnorm[warp] = s;
}

// ---------------------------------------------------------------------------
// argmin via mma.sync, merged 3-pass stages:
// flat loop over 64 k-stages (8 chunks x 8 stages). Per stage: load A-hi,
// A-lo, B-hi, B-lo fragments once, issue 96 MMAs (hi*hi + lo*hi + hi*lo).
// B streamed through a 4-deep 16KB ring (prefetch distance 3).
// ---------------------------------------------------------------------------
__global__ __launch_bounds__(256, 1) void argmin_mma() {
    extern __shared__ __align__(128) unsigned char smem[];
    const uint32_t sb = smem_u32(smem);
    const int tid = threadIdx.x, lane = tid & 31, wid = tid >> 5;
    const int wm = wid & 1, wn = wid >> 1;
    const int bm = blockIdx.x;

    float* sm_cn = reinterpret_cast<float*>(smem + SM_CN);
    unsigned long long* sBest = reinterpret_cast<unsigned long long*>(smem + SM_BEST);
    for (int i = tid; i < Kc; i += 256) sm_cn[i] = g_cnorm[i];
    if (tid < 128) sBest[tid] = ~0ull;

    // A image -> smem (group 0)
    {
        const unsigned char* src = gA + (size_t)bm * 131072;
        #pragma unroll
        for (int v = 0; v < 32; v++) {
            int id = v * 256 + tid;
            int tile = id >> 9, r = (id >> 2) & 127, u = id & 3;
            uint32_t dst = sb + SM_A + tile * 8192 + r * 64 + 16 * (u ^ ((r >> 1) & 3));
            cp16(dst, src + (size_t)id * 16);
        }
        cp_commit();
    }

    auto issueB = [&](int t) {
        int nc = t >> 3, s = t & 7;
        uint32_t buf = sb + SM_B + (t & 3) * 16384;
        const unsigned char* srcHi = gB + ((size_t)(nc * 2 + 0) * 8 + s) * 8192;
        const unsigned char* srcLo = gB + ((size_t)(nc * 2 + 1) * 8 + s) * 8192;
        #pragma unroll
        for (int v = 0; v < 2; v++) {
            int id = v * 256 + tid;
            int r = id >> 2, u = id & 3;
            uint32_t off = r * 64 + 16 * (u ^ ((r >> 1) & 3));
            cp16(buf + off, srcHi + (size_t)id * 16);
            cp16(buf + 8192 + off, srcLo + (size_t)id * 16);
        }
        cp_commit();
    };

    issueB(0); issueB(1); issueB(2);

    // lane-fixed fragment address components
    const int a_r = wm * 64 + (lane & 15);                       // + mi*16
    const int a_u = lane >> 4;                                   // + kk*2
    const int b_r = wn * 32 + (lane & 7) + ((lane >> 4) << 3);   // + np*16
    const int b_u = (lane >> 3) & 1;                             // + kk*2

    float best8[8];
    int   bid8[8];
    #pragma unroll
    for (int i = 0; i < 8; i++) { best8[i] = 3.4e38f; bid8[i] = 0; }

    float acc[4][4][4];
    #pragma unroll
    for (int mi = 0; mi < 4; mi++)
        #pragma unroll
        for (int ni = 0; ni < 4; ni++)
            #pragma unroll
            for (int c = 0; c < 4; c++) acc[mi][ni][c] = 0.f;

    #pragma unroll 1
    for (int t = 0; t < TSTAGE; t++) {
        if (t <= TSTAGE - 3)      cp_wait2();
        else if (t == TSTAGE - 2) cp_wait1();
        else                      cp_wait0();
        __syncthreads();
        if (t + 3 < TSTAGE) issueB(t + 3);

        const int s = t & 7;
        const uint32_t bufhi = sb + SM_B + (t & 3) * 16384;
        const uint32_t buflo = bufhi + 8192;
        const uint32_t SAhi  = sb + SM_A + s * 8192;
        const uint32_t SAlo  = SAhi + 65536;

        #pragma unroll
        for (int kk = 0; kk < 2; kk++) {
            uint32_t bh[8], bl[8], ah[16], al[16];
            #pragma unroll
            for (int np = 0; np < 2; np++) {
                int r = b_r + np * 16;
                int c = kk * 2 + b_u;
                uint32_t off = r * 64 + 16 * (c ^ ((r >> 1) & 3));
                ldsm4(bh[np*4+0], bh[np*4+1], bh[np*4+2], bh[np*4+3], bufhi + off);
                ldsm4(bl[np*4+0], bl[np*4+1], bl[np*4+2], bl[np*4+3], buflo + off);
            }
            #pragma unroll
            for (int mi = 0; mi < 4; mi++) {
                int r = a_r + mi * 16;
                int c = kk * 2 + a_u;
                uint32_t off = r * 64 + 16 * (c ^ ((r >> 1) & 3));
                ldsm4(ah[mi*4+0], ah[mi*4+1], ah[mi*4+2], ah[mi*4+3], SAhi + off);
                ldsm4(al[mi*4+0], al[mi*4+1], al[mi*4+2], al[mi*4+3], SAlo + off);
            }
            // pass 1: A-hi * B-hi
            #pragma unroll
            for (int mi = 0; mi < 4; mi++)
                #pragma unroll
                for (int ni = 0; ni < 4; ni++)
                    mma16816(acc[mi][ni][0], acc[mi][ni][1], acc[mi][ni][2], acc[mi][ni][3],
                             ah[mi*4+0], ah[mi*4+1], ah[mi*4+2], ah[mi*4+3],
                             bh[(ni>>1)*4 + (ni&1)*2], bh[(ni>>1)*4 + (ni&1)*2 + 1]);
            // pass 2: A-lo * B-hi
            #pragma unroll
            for (int mi = 0; mi < 4; mi++)
                #pragma unroll
                for (int ni = 0; ni < 4; ni++)
                    mma16816(acc[mi][ni][0], acc[mi][ni][1], acc[mi][ni][2], acc[mi][ni][3],
                             al[mi*4+0], al[mi*4+1], al[mi*4+2], al[mi*4+3],
                             bh[(ni>>1)*4 + (ni&1)*2], bh[(ni>>1)*4 + (ni&1)*2 + 1]);
            // pass 3: A-hi * B-lo
            #pragma unroll
            for (int mi = 0; mi < 4; mi++)
                #pragma unroll
                for (int ni = 0; ni < 4; ni++)
                    mma16816(acc[mi][ni][0], acc[mi][ni][1], acc[mi][ni][2], acc[mi][ni][3],
                             ah[mi*4+0], ah[mi*4+1], ah[mi*4+2], ah[mi*4+3],
                             bl[(ni>>1)*4 + (ni&1)*2], bl[(ni>>1)*4 + (ni&1)*2 + 1]);
        }

        if (s == 7) {
            const int nc = t >> 3;
            #pragma unroll
            for (int mi = 0; mi < 4; mi++)
                #pragma unroll
                for (int ni = 0; ni < 4; ni++)
                    #pragma unroll
                    for (int c = 0; c < 4; c++) {
                        int code = nc * 128 + wn * 32 + ni * 8 + (lane & 3) * 2 + (c & 1);
                        float score = fmaf(-2.f, acc[mi][ni][c], sm_cn[code]);
                        int slot = mi * 2 + (c >> 1);
                        if (score < best8[slot]) { best8[slot] = score; bid8[slot] = code; }
                        acc[mi][ni][c] = 0.f;
                    }
        }
    }

    __syncthreads();
    #pragma unroll
    for (int slot = 0; slot < 8; slot++) {
        int row = wm * 64 + (slot >> 1) * 16 + (lane >> 2) + 8 * (slot & 1);
        unsigned long long pack =
            ((unsigned long long)fkey(best8[slot]) << 32) | (unsigned int)bid8[slot];
        atomicMin(&sBest[row], pack);
    }
    __syncthreads();
    if (tid < 128)
        g_idx[bm * M_TILE + tid] = (int)(unsigned int)(sBest[tid] & 0xFFFFFFFFull);
}

// ---------------------------------------------------------------------------
__global__ void output_kernel(const float* __restrict__ x,
                              const float* __restrict__ cb,
                              float* __restrict__ zhat,
                              float* __restrict__ zq)
{
    int t = blockIdx.x * blockDim.x + threadIdx.x;
    if (t >= NELEM / 4) return;
    int n  = t >> 6;
    int d4 = t & 63;
    int k  = g_idx[n];
    float4 c  = *reinterpret_cast<const float4*>(cb + (size_t)k * Dc + d4 * 4);
    float4 xv = *reinterpret_cast<const float4*>(x + (size_t)t * 4);
    float4 zh;
    zh.x = xv.x + (c.x - xv.x);
    zh.y = xv.y + (c.y - xv.y);
    zh.z = xv.z + (c.z - xv.z);
    zh.w = xv.w + (c.w - xv.w);
    *reinterpret_cast<float4*>(zq   + (size_t)t * 4) = c;
    *reinterpret_cast<float4*>(zhat + (size_t)t * 4) = zh;
}

// ---------------------------------------------------------------------------
extern "C" void kernel_launch(void* const* d_in, const int* in_sizes, int n_in,
                              void* d_out, int out_size)
{
    const float* x  = (const float*)d_in[0];
    const float* cb = (const float*)d_in[1];
    float* zhat = (float*)d_out;
    float* zq   = (float*)d_out + NELEM;

    static int attr_set = 0;
    if (!attr_set) {
        cudaFuncSetAttribute(argmin_mma, cudaFuncAttributeMaxDynamicSharedMemorySize, SM_TOTAL);
        attr_set = 1;
    }

    prep_a<<<dim3(NBLK, NSTG), 256>>>(x);
    prep_b<<<dim3(8, NSTG), 256>>>(cb);
    cnorm_kernel<<<Kc / 8, 256>>>(cb);
    argmin_mma<<<NBLK, 256, SM_TOTAL>>>();
    output_kernel<<<(NELEM / 4 + 255) / 256, 256>>>(x, cb, zhat, zq);
}